// round 12
// baseline (speedup 1.0000x reference)
#include <cuda_runtime.h>
#include <stdint.h>
#include <math.h>

// ---------------------------------------------------------------------------
// TripletLossWithCurvature: B=8192, D=512, classes<100
// Bit-exact JAX Threefry-2x32 (partitionable mode).
// R10: k_neg adds forced to IMAD (opaque 'one'; no IMAD.WIDE — that was R8's
// regression, rt=4), parallel k_labels (8 blocks), k_pos on its own stream
// so it overlaps k_neg. ILP4 k_neg, FFMA2 GEMMs, triangular SYRK kept.
// ---------------------------------------------------------------------------
#define BB 8192
#define DD 512
#define NCLS 128

__device__ float g_S[DD*DD];
__device__ float g_G[DD*DD];
__device__ float g_H[BB*DD];
__device__ float g_q[BB];
__device__ float g_musum[DD];
__device__ int   g_lab[BB];
__device__ unsigned char g_lab8[BB];
__device__ int   g_cnt[NCLS];
__device__ int   g_off[NCLS];
__device__ int   g_fill[NCLS];
__device__ int   g_list[BB];
__device__ int   g_pos[BB];
__device__ int   g_neg[BB];
__device__ float g_acc[2];

// ---------------------------------------------------------------------------
// Packed fp32 helpers (exact per-lane IEEE fp32)
// ---------------------------------------------------------------------------
__device__ __forceinline__ void ffma2(unsigned long long &acc,
                                      unsigned long long a2,
                                      unsigned long long b2) {
  asm("fma.rn.f32x2 %0, %1, %2, %0;" : "+l"(acc) : "l"(a2), "l"(b2));
}
__device__ __forceinline__ unsigned long long pack2(float x) {
  unsigned long long r;
  unsigned int xi = __float_as_uint(x);
  asm("mov.b64 %0, {%1, %1};" : "=l"(r) : "r"(xi));
  return r;
}
union U64F2 { unsigned long long u; float2 f; };

// ---------------------------------------------------------------------------
// Threefry-2x32, 20 rounds — plain C version (k_pos)
// ---------------------------------------------------------------------------
__device__ __forceinline__ void tf_block(uint32_t k0, uint32_t k1,
                                         uint32_t &x0, uint32_t &x1) {
  uint32_t ks2 = k0 ^ k1 ^ 0x1BD11BDAu;
  x0 += k0; x1 += k1;
#define TF_ROT(x,r) (((x) << (r)) | ((x) >> (32 - (r))))
#define TF_RND(r) { x0 += x1; x1 = TF_ROT(x1, r); x1 ^= x0; }
  TF_RND(13) TF_RND(15) TF_RND(26) TF_RND(6)
  x0 += k1;  x1 += ks2 + 1u;
  TF_RND(17) TF_RND(29) TF_RND(16) TF_RND(24)
  x0 += ks2; x1 += k0 + 2u;
  TF_RND(13) TF_RND(15) TF_RND(26) TF_RND(6)
  x0 += k0;  x1 += k1 + 3u;
  TF_RND(17) TF_RND(29) TF_RND(16) TF_RND(24)
  x0 += k1;  x1 += ks2 + 4u;
  TF_RND(13) TF_RND(15) TF_RND(26) TF_RND(6)
  x0 += ks2; x1 += k0 + 5u;
#undef TF_RND
#undef TF_ROT
}

__device__ __forceinline__ uint32_t draw_bits(uint32_t k0, uint32_t k1, uint32_t p) {
  uint32_t x0 = 0u, x1 = p;
  tf_block(k0, k1, x0, x1);
  return x0 ^ x1;
}

// k_neg draw: identical op semantics/count, but every x0-add forced onto the
// fma pipe (IMAD via mad.lo with runtime-opaque 'one'). Rotates stay SHF.
__device__ __forceinline__ uint32_t draw_neg(uint32_t k0, uint32_t k1,
                                             uint32_t p, uint32_t one) {
  uint32_t ks2 = k0 ^ k1 ^ 0x1BD11BDAu;
  uint32_t x0 = k0, x1 = p + k1;
#define ADDI(d, s) asm("mad.lo.u32 %0, %1, %2, %0;" : "+r"(d) : "r"(s), "r"(one))
#define RS(r) { ADDI(x0, x1); x1 = __funnelshift_l(x1, x1, r) ^ x0; }
  RS(13) RS(15) RS(26) RS(6)
  ADDI(x0, k1);  x1 += ks2 + 1u;
  RS(17) RS(29) RS(16) RS(24)
  ADDI(x0, ks2); x1 += k0 + 2u;
  RS(13) RS(15) RS(26) RS(6)
  ADDI(x0, k0);  x1 += k1 + 3u;
  RS(17) RS(29) RS(16) RS(24)
  ADDI(x0, k1);  x1 += ks2 + 4u;
  RS(13) RS(15) RS(26) RS(6)
  ADDI(x0, ks2); x1 += k0 + 5u;
#undef RS
#undef ADDI
  return x0 ^ x1;
}

// Compile-time subkeys: split(key(42)) blocks on counts 0/1.
struct K2 { uint32_t a, b; };
constexpr uint32_t c_rotl(uint32_t x, int r) {
  return (x << r) | (x >> (32 - r));
}
constexpr K2 tf_pair(uint32_t k0, uint32_t k1, uint32_t c0, uint32_t c1) {
  uint32_t ks2 = k0 ^ k1 ^ 0x1BD11BDAu;
  uint32_t x0 = c0 + k0, x1 = c1 + k1;
#define CR(r) x0 += x1; x1 = c_rotl(x1, r); x1 ^= x0;
  CR(13) CR(15) CR(26) CR(6)
  x0 += k1;  x1 += ks2 + 1u;
  CR(17) CR(29) CR(16) CR(24)
  x0 += ks2; x1 += k0 + 2u;
  CR(13) CR(15) CR(26) CR(6)
  x0 += k0;  x1 += k1 + 3u;
  CR(17) CR(29) CR(16) CR(24)
  x0 += k1;  x1 += ks2 + 4u;
  CR(13) CR(15) CR(26) CR(6)
  x0 += ks2; x1 += k0 + 5u;
#undef CR
  return K2{x0, x1};
}
constexpr K2 KP = tf_pair(0u, 42u, 0u, 0u);
constexpr K2 KN = tf_pair(0u, 42u, 0u, 1u);

// ---------------------------------------------------------------------------
// Kernels
// ---------------------------------------------------------------------------
__global__ void k_zero() {
  int idx = blockIdx.x * blockDim.x + threadIdx.x;
  int stride = gridDim.x * blockDim.x;
  for (int i = idx; i < DD*DD; i += stride) g_S[i] = 0.f;
  if (idx < DD) g_musum[idx] = 0.f;
}

// Zero sampling counters (runs before the parallel histogram).
__global__ void k_zs() {
  int t = threadIdx.x;
  if (t < NCLS) g_cnt[t] = 0;
  if (t < 2)    g_acc[t] = 0.f;
}

// Parallel label decode + histogram: 8 blocks x 1024 threads, 1024 labels each.
__global__ void k_labels(const void* __restrict__ lraw) {
  __shared__ int s_is64;
  if (threadIdx.x == 0) s_is64 = 1;
  __syncthreads();
  const int* w = (const int*)lraw;
  int b = blockIdx.x;
  // int64 detection on this block's 512-pair slice of the first 4096 pairs
  // (valid reads for both int32[8192] and int64[8192] layouts).
  if (threadIdx.x < 512) {
    int k = b * 512 + threadIdx.x;
    if (w[2*k + 1] != 0) s_is64 = 0;
  }
  __syncthreads();
  int is64 = s_is64;
  int i = b * 1024 + threadIdx.x;
  int lab = is64 ? (int)(((const long long*)lraw)[i]) : w[i];
  if (lab < 0) lab = 0;
  if (lab >= NCLS) lab = NCLS - 1;
  g_lab[i]  = lab;
  g_lab8[i] = (unsigned char)lab;
  atomicAdd(&g_cnt[lab], 1);
}

__global__ void k_offsets() {
  if (threadIdx.x == 0 && blockIdx.x == 0) {
    int acc = 0;
    for (int c = 0; c < NCLS; c++) { g_off[c] = acc; g_fill[c] = acc; acc += g_cnt[c]; }
  }
}

__global__ void k_scatter() {
  int i = blockIdx.x * blockDim.x + threadIdx.x;
  if (i < BB) {
    int lab = g_lab[i];
    int p = atomicAdd(&g_fill[lab], 1);
    g_list[p] = i;
  }
}

// Positive sampling: one warp per row; g_list unsorted -> full tie-break.
__global__ void k_pos() {
  int w = (blockIdx.x * blockDim.x + threadIdx.x) >> 5;
  int lane = threadIdx.x & 31;
  if (w >= BB) return;
  int i = w;
  int lab = g_lab[i];
  int off = g_off[lab], cnt = g_cnt[lab];
  uint32_t base = (uint32_t)i * (uint32_t)BB;
  uint32_t bestv = 0u; int bestj = 0; int any = 0;
  for (int c = lane; c < cnt; c += 32) {
    int j = g_list[off + c];
    if (j == i) continue;
    uint32_t v = draw_bits(KP.a, KP.b, base + (uint32_t)j) >> 9;
    if (!any || v > bestv || (v == bestv && j < bestj)) { any = 1; bestv = v; bestj = j; }
  }
  for (int o = 16; o; o >>= 1) {
    uint32_t ov = __shfl_down_sync(0xffffffffu, bestv, o);
    int      oj = __shfl_down_sync(0xffffffffu, bestj, o);
    int      oa = __shfl_down_sync(0xffffffffu, any,  o);
    if (oa && (!any || ov > bestv || (ov == bestv && oj < bestj))) {
      any = 1; bestv = ov; bestj = oj;
    }
  }
  if (lane == 0) g_pos[i] = bestj;
}

// Negative sampling: one block per row; 4 independent chains per thread per
// iteration (ILP), branchless masking, IMAD-forced adds. Ascending j per
// thread -> strict > preserves first-occurrence argmax.
__global__ void k_neg(uint32_t one) {
  __shared__ unsigned char slab[BB];
  __shared__ uint32_t sv[256];
  __shared__ int sj[256];
  int i = blockIdx.x, t = threadIdx.x;
  {
    const uint32_t* l4 = (const uint32_t*)g_lab8;
    uint32_t* s4 = (uint32_t*)slab;
    for (int j = t; j < BB / 4; j += 256) s4[j] = l4[j];
  }
  __syncthreads();
  unsigned char mylab = slab[i];
  uint32_t base = (uint32_t)i * (uint32_t)BB;
  uint32_t bestv = 0u; int bestj = -1;
#pragma unroll
  for (int s = 0; s < 8; s++) {
    int j0 = t + s * 1024;
    int j1 = j0 + 256, j2 = j0 + 512, j3 = j0 + 768;
    uint32_t d0 = draw_neg(KN.a, KN.b, base + (uint32_t)j0, one);
    uint32_t d1 = draw_neg(KN.a, KN.b, base + (uint32_t)j1, one);
    uint32_t d2 = draw_neg(KN.a, KN.b, base + (uint32_t)j2, one);
    uint32_t d3 = draw_neg(KN.a, KN.b, base + (uint32_t)j3, one);
    uint32_t v0 = (slab[j0] == mylab) ? 0u : (d0 >> 9);
    uint32_t v1 = (slab[j1] == mylab) ? 0u : (d1 >> 9);
    uint32_t v2 = (slab[j2] == mylab) ? 0u : (d2 >> 9);
    uint32_t v3 = (slab[j3] == mylab) ? 0u : (d3 >> 9);
    if (v0 > bestv) { bestv = v0; bestj = j0; }
    if (v1 > bestv) { bestv = v1; bestj = j1; }
    if (v2 > bestv) { bestv = v2; bestj = j2; }
    if (v3 > bestv) { bestv = v3; bestj = j3; }
  }
  sv[t] = bestv; sj[t] = bestj;
  __syncthreads();
  for (int s = 128; s; s >>= 1) {
    if (t < s) {
      uint32_t ov = sv[t + s]; int oj = sj[t + s];
      if (oj >= 0 && (sj[t] < 0 || ov > sv[t] || (ov == sv[t] && oj < sj[t]))) {
        sv[t] = ov; sj[t] = oj;
      }
    }
    __syncthreads();
  }
  if (t == 0) g_neg[i] = (sj[0] >= 0) ? sj[0] : 0;
}

__global__ void k_mu(const float* __restrict__ F) {
  int c = threadIdx.x;
  int r0 = blockIdx.x * 128;
  float s = 0.f;
  for (int r = 0; r < 128; r++) s += F[(size_t)(r0 + r) * DD + c];
  atomicAdd(&g_musum[c], s);
}

// S = F^T F, upper-triangle 64x64 block tiles (36), split-K (z=8), FFMA2.
__global__ void k_syrk(const float* __restrict__ F) {
  __shared__ float As[16][64];
  __shared__ float Bs[16][64];
  int rem = blockIdx.x, bi = 0;
  while (rem >= 8 - bi) { rem -= 8 - bi; bi++; }
  int bj = bi + rem;
  int i0 = bi * 64, j0 = bj * 64;
  int kb = blockIdx.z * 1024;
  int t = threadIdx.x;
  int tx = t & 15, ty = t >> 4;
  unsigned long long acc2[4][2];
#pragma unroll
  for (int u = 0; u < 4; u++) { acc2[u][0] = 0ull; acc2[u][1] = 0ull; }

  for (int k = kb; k < kb + 1024; k += 16) {
#pragma unroll
    for (int r = 0; r < 4; r++) {
      int e = t + 256 * r, kk = e >> 6, c = e & 63;
      As[kk][c] = F[(size_t)(k + kk) * DD + i0 + c];
      Bs[kk][c] = F[(size_t)(k + kk) * DD + j0 + c];
    }
    __syncthreads();
#pragma unroll
    for (int kk = 0; kk < 16; kk++) {
      unsigned long long aa[4], bb[2];
      const unsigned long long* bp = (const unsigned long long*)&Bs[kk][tx * 4];
      bb[0] = bp[0]; bb[1] = bp[1];
#pragma unroll
      for (int u = 0; u < 4; u++) aa[u] = pack2(As[kk][ty * 4 + u]);
#pragma unroll
      for (int u = 0; u < 4; u++) {
        ffma2(acc2[u][0], aa[u], bb[0]);
        ffma2(acc2[u][1], aa[u], bb[1]);
      }
    }
    __syncthreads();
  }
#pragma unroll
  for (int u = 0; u < 4; u++) {
#pragma unroll
    for (int v2 = 0; v2 < 2; v2++) {
      U64F2 cv; cv.u = acc2[u][v2];
      size_t row = (size_t)(i0 + ty * 4 + u) * DD + j0 + tx * 4 + v2 * 2;
      atomicAdd(&g_S[row],     cv.f.x);
      atomicAdd(&g_S[row + 1], cv.f.y);
    }
  }
}

__global__ void k_makeG() {
  int i = blockIdx.x, j = threadIdx.x;
  const float invB = 1.0f / (float)BB;
  float mui = g_musum[i] * invB;
  float muj = g_musum[j] * invB;
  float s = (i <= j) ? g_S[(size_t)i * DD + j] : g_S[(size_t)j * DD + i];
  float v = s * invB - mui * muj + (i == j ? 1.0f : 0.0f);
  g_G[(size_t)i * DD + j] = v;
}

// H = F * G  (8192x512 @ 512x512), FFMA2 inner loop.
__global__ void k_gemmH(const float* __restrict__ F) {
  __shared__ float As[16][65];
  __shared__ float Bs[16][64];
  int m0 = blockIdx.x * 64, n0 = blockIdx.y * 64;
  int t = threadIdx.x, tx = t & 15, ty = t >> 4;
  unsigned long long acc2[4][2];
#pragma unroll
  for (int u = 0; u < 4; u++) { acc2[u][0] = 0ull; acc2[u][1] = 0ull; }

  for (int k = 0; k < DD; k += 16) {
#pragma unroll
    for (int r = 0; r < 4; r++) {
      int e = t + 256 * r;
      int kk = e & 15, mm = e >> 4;
      As[kk][mm] = F[(size_t)(m0 + mm) * DD + k + kk];
    }
#pragma unroll
    for (int r = 0; r < 4; r++) {
      int e = t + 256 * r, kk = e >> 6, c = e & 63;
      Bs[kk][c] = g_G[(size_t)(k + kk) * DD + n0 + c];
    }
    __syncthreads();
#pragma unroll
    for (int kk = 0; kk < 16; kk++) {
      unsigned long long aa[4], bb[2];
      const unsigned long long* bp = (const unsigned long long*)&Bs[kk][tx * 4];
      bb[0] = bp[0]; bb[1] = bp[1];
#pragma unroll
      for (int u = 0; u < 4; u++) aa[u] = pack2(As[kk][ty * 4 + u]);
#pragma unroll
      for (int u = 0; u < 4; u++) {
        ffma2(acc2[u][0], aa[u], bb[0]);
        ffma2(acc2[u][1], aa[u], bb[1]);
      }
    }
    __syncthreads();
  }
#pragma unroll
  for (int u = 0; u < 4; u++) {
    U64F2 lo, hi; lo.u = acc2[u][0]; hi.u = acc2[u][1];
    float4 o; o.x = lo.f.x; o.y = lo.f.y; o.z = hi.f.x; o.w = hi.f.y;
    *(float4*)&g_H[(size_t)(m0 + ty * 4 + u) * DD + n0 + tx * 4] = o;
  }
}

__global__ void k_q(const float* __restrict__ F) {
  int w = (blockIdx.x * blockDim.x + threadIdx.x) >> 5;
  int lane = threadIdx.x & 31;
  if (w >= BB) return;
  const float* f = F + (size_t)w * DD;
  const float* h = g_H + (size_t)w * DD;
  float s = 0.f;
  for (int c = lane; c < DD; c += 32) s += f[c] * h[c];
  for (int o = 16; o; o >>= 1) s += __shfl_down_sync(0xffffffffu, s, o);
  if (lane == 0) g_q[w] = s;
}

__global__ void k_loss(const float* __restrict__ F) {
  __shared__ float rp[128], rn[128];
  int i = blockIdx.x, t = threadIdx.x;
  int p = g_pos[i], n = g_neg[i];
  float sp = 0.f, sn = 0.f;
  const float* f  = F   + (size_t)i * DD;
  const float* hp = g_H + (size_t)p * DD;
  const float* hn = g_H + (size_t)n * DD;
  for (int c = t; c < DD; c += 128) {
    float fv = f[c];
    sp += fv * hp[c];
    sn += fv * hn[c];
  }
  rp[t] = sp; rn[t] = sn;
  __syncthreads();
  for (int s = 64; s; s >>= 1) {
    if (t < s) { rp[t] += rp[t + s]; rn[t] += rn[t + s]; }
    __syncthreads();
  }
  if (t == 0) {
    int lab = g_lab[i];
    int cnt = g_cnt[lab];
    bool valid = (cnt >= 2) && (cnt < BB);
    if (valid) {
      float dp = sqrtf(g_q[i] + g_q[p] - 2.0f * rp[0] + 1e-8f);
      float dn = sqrtf(g_q[i] + g_q[n] - 2.0f * rn[0] + 1e-8f);
      float per = fmaxf(dp - dn + 1.0f, 0.0f);
      atomicAdd(&g_acc[0], per);
      atomicAdd(&g_acc[1], 1.0f);
    }
  }
}

__global__ void k_final(float* __restrict__ out) {
  out[0] = g_acc[0] / fmaxf(g_acc[1], 1.0f);
}

// ---------------------------------------------------------------------------
extern "C" void kernel_launch(void* const* d_in, const int* in_sizes, int n_in,
                              void* d_out, int out_size) {
  const float* F = (const float*)d_in[0];
  const void*  L = d_in[1];
  float* out = (float*)d_out;

  static cudaStream_t s_neg = nullptr, s_pos = nullptr;
  static cudaEvent_t  ev_fork = nullptr, ev_lab = nullptr,
                      ev_jn = nullptr, ev_jp = nullptr;
  if (s_neg == nullptr) {
    cudaStreamCreateWithFlags(&s_neg, cudaStreamNonBlocking);
    cudaStreamCreateWithFlags(&s_pos, cudaStreamNonBlocking);
    cudaEventCreateWithFlags(&ev_fork, cudaEventDisableTiming);
    cudaEventCreateWithFlags(&ev_lab,  cudaEventDisableTiming);
    cudaEventCreateWithFlags(&ev_jn,   cudaEventDisableTiming);
    cudaEventCreateWithFlags(&ev_jp,   cudaEventDisableTiming);
  }

  const uint32_t one = (uint32_t)(n_in > 0);   // runtime-opaque 1

  // sampling fork
  cudaEventRecord(ev_fork, 0);
  cudaStreamWaitEvent(s_neg, ev_fork, 0);
  k_zs<<<1, 128, 0, s_neg>>>();
  k_labels<<<8, 1024, 0, s_neg>>>(L);
  cudaEventRecord(ev_lab, s_neg);
  k_neg<<<BB, 256, 0, s_neg>>>(one);
  cudaEventRecord(ev_jn, s_neg);

  // pos chain concurrent with k_neg
  cudaStreamWaitEvent(s_pos, ev_lab, 0);
  k_offsets<<<1, 32, 0, s_pos>>>();
  k_scatter<<<32, 256, 0, s_pos>>>();
  k_pos<<<BB / 8, 256, 0, s_pos>>>();
  cudaEventRecord(ev_jp, s_pos);

  // metric chain on the main stream
  k_zero<<<256, 256>>>();
  k_mu<<<64, 512>>>(F);
  {
    dim3 g(36, 1, 8);
    k_syrk<<<g, 256>>>(F);
  }
  k_makeG<<<512, 512>>>();
  {
    dim3 g(128, 8);
    k_gemmH<<<g, 256>>>(F);
  }
  k_q<<<BB / 8, 256>>>(F);

  cudaStreamWaitEvent(0, ev_jn, 0);
  cudaStreamWaitEvent(0, ev_jp, 0);
  k_loss<<<BB, 128>>>(F);
  k_final<<<1, 1>>>(out);
}

// round 16
// speedup vs baseline: 1.0375x; 1.0375x over previous
#include <cuda_runtime.h>
#include <stdint.h>
#include <math.h>

// ---------------------------------------------------------------------------
// TripletLossWithCurvature: B=8192, D=512, classes<100
// Bit-exact JAX Threefry-2x32 (partitionable mode).
// R14: R9 baseline (best: 401.6us) + merged k_build (offsets+scatter via
// shuffle-scan; k_offsets alone measured 9.3us) + parallel k_labels.
// tcgen05 is OFF THE TABLE: harness PTX target is sm_103 (no 'a' suffix),
// all tcgen05/TMEM instructions fail ptxas. SIMT-only optimization space.
// ---------------------------------------------------------------------------
#define BB 8192
#define DD 512
#define NCLS 128

__device__ float g_S[DD*DD];
__device__ float g_G[DD*DD];
__device__ float g_H[BB*DD];
__device__ float g_q[BB];
__device__ float g_musum[DD];
__device__ int   g_lab[BB];
__device__ unsigned char g_lab8[BB];
__device__ int   g_cnt[NCLS];
__device__ int   g_off[NCLS];
__device__ int   g_list[BB];
__device__ int   g_pos[BB];
__device__ int   g_neg[BB];
__device__ float g_acc[2];

// ---------------------------------------------------------------------------
// Packed fp32 helpers (exact per-lane IEEE fp32)
// ---------------------------------------------------------------------------
__device__ __forceinline__ void ffma2(unsigned long long &acc,
                                      unsigned long long a2,
                                      unsigned long long b2) {
  asm("fma.rn.f32x2 %0, %1, %2, %0;" : "+l"(acc) : "l"(a2), "l"(b2));
}
__device__ __forceinline__ unsigned long long pack2(float x) {
  unsigned long long r;
  unsigned int xi = __float_as_uint(x);
  asm("mov.b64 %0, {%1, %1};" : "=l"(r) : "r"(xi));
  return r;
}
union U64F2 { unsigned long long u; float2 f; };

// ---------------------------------------------------------------------------
// Threefry-2x32, 20 rounds — plain C (ptxas schedules this best; forced
// IMAD/IMAD.WIDE variants regressed in R8 and R12)
// ---------------------------------------------------------------------------
__device__ __forceinline__ void tf_block(uint32_t k0, uint32_t k1,
                                         uint32_t &x0, uint32_t &x1) {
  uint32_t ks2 = k0 ^ k1 ^ 0x1BD11BDAu;
  x0 += k0; x1 += k1;
#define TF_ROT(x,r) (((x) << (r)) | ((x) >> (32 - (r))))
#define TF_RND(r) { x0 += x1; x1 = TF_ROT(x1, r); x1 ^= x0; }
  TF_RND(13) TF_RND(15) TF_RND(26) TF_RND(6)
  x0 += k1;  x1 += ks2 + 1u;
  TF_RND(17) TF_RND(29) TF_RND(16) TF_RND(24)
  x0 += ks2; x1 += k0 + 2u;
  TF_RND(13) TF_RND(15) TF_RND(26) TF_RND(6)
  x0 += k0;  x1 += k1 + 3u;
  TF_RND(17) TF_RND(29) TF_RND(16) TF_RND(24)
  x0 += k1;  x1 += ks2 + 4u;
  TF_RND(13) TF_RND(15) TF_RND(26) TF_RND(6)
  x0 += ks2; x1 += k0 + 5u;
#undef TF_RND
#undef TF_ROT
}
__device__ __forceinline__ uint32_t draw_bits(uint32_t k0, uint32_t k1, uint32_t p) {
  uint32_t x0 = 0u, x1 = p;
  tf_block(k0, k1, x0, x1);
  return x0 ^ x1;
}
struct K2 { uint32_t a, b; };
constexpr uint32_t c_rotl(uint32_t x, int r) { return (x << r) | (x >> (32 - r)); }
constexpr K2 tf_pair(uint32_t k0, uint32_t k1, uint32_t c0, uint32_t c1) {
  uint32_t ks2 = k0 ^ k1 ^ 0x1BD11BDAu;
  uint32_t x0 = c0 + k0, x1 = c1 + k1;
#define CR(r) x0 += x1; x1 = c_rotl(x1, r); x1 ^= x0;
  CR(13) CR(15) CR(26) CR(6)
  x0 += k1;  x1 += ks2 + 1u;
  CR(17) CR(29) CR(16) CR(24)
  x0 += ks2; x1 += k0 + 2u;
  CR(13) CR(15) CR(26) CR(6)
  x0 += k0;  x1 += k1 + 3u;
  CR(17) CR(29) CR(16) CR(24)
  x0 += k1;  x1 += ks2 + 4u;
  CR(13) CR(15) CR(26) CR(6)
  x0 += ks2; x1 += k0 + 5u;
#undef CR
  return K2{x0, x1};
}
constexpr K2 KP = tf_pair(0u, 42u, 0u, 0u);   // positive-sampling key
constexpr K2 KN = tf_pair(0u, 42u, 0u, 1u);   // negative-sampling key

// ---------------------------------------------------------------------------
// Kernels
// ---------------------------------------------------------------------------
__global__ void k_zero() {
  int idx = blockIdx.x * blockDim.x + threadIdx.x;
  int stride = gridDim.x * blockDim.x;
  for (int i = idx; i < DD*DD; i += stride) g_S[i] = 0.f;
  if (idx < DD) g_musum[idx] = 0.f;
}

// Zero sampling counters (before the parallel histogram).
__global__ void k_zs() {
  int t = threadIdx.x;
  if (t < NCLS) g_cnt[t] = 0;
  if (t < 2)    g_acc[t] = 0.f;
}

// Parallel label decode + histogram: 8 blocks x 1024 threads (ran correctly
// in R12; that round's regression was the draw_neg IMAD variant).
__global__ void k_labels(const void* __restrict__ lraw) {
  __shared__ int s_is64;
  if (threadIdx.x == 0) s_is64 = 1;
  __syncthreads();
  const int* w = (const int*)lraw;
  int b = blockIdx.x;
  // int64 detection on this block's 512-pair slice of the first 4096 pairs
  // (valid reads under both int32[8192] and int64[8192] layouts).
  if (threadIdx.x < 512) {
    int k = b * 512 + threadIdx.x;
    if (w[2*k + 1] != 0) s_is64 = 0;
  }
  __syncthreads();
  int is64 = s_is64;
  int i = b * 1024 + threadIdx.x;
  int lab = is64 ? (int)(((const long long*)lraw)[i]) : w[i];
  if (lab < 0) lab = 0;
  if (lab >= NCLS) lab = NCLS - 1;
  g_lab[i]  = lab;
  g_lab8[i] = (unsigned char)lab;
  atomicAdd(&g_cnt[lab], 1);
}

// Merged offsets (warp shuffle-scan over 128 counts) + scatter. One block.
__global__ void k_build() {
  __shared__ int s_fill[NCLS];
  int t = threadIdx.x;
  if (t < 32) {
    int c0 = g_cnt[4*t], c1 = g_cnt[4*t+1], c2 = g_cnt[4*t+2], c3 = g_cnt[4*t+3];
    int s = c0 + c1 + c2 + c3;
    int scan = s;
    for (int o = 1; o < 32; o <<= 1) {
      int n = __shfl_up_sync(0xffffffffu, scan, o);
      if (t >= o) scan += n;
    }
    int e = scan - s;                 // exclusive prefix of the 4-group
    g_off[4*t]   = e;                s_fill[4*t]   = e;
    g_off[4*t+1] = e + c0;           s_fill[4*t+1] = e + c0;
    g_off[4*t+2] = e + c0 + c1;      s_fill[4*t+2] = e + c0 + c1;
    g_off[4*t+3] = e + c0 + c1 + c2; s_fill[4*t+3] = e + c0 + c1 + c2;
  }
  __syncthreads();
  for (int i = t; i < BB; i += 1024) {
    int lab = g_lab[i];
    int p = atomicAdd(&s_fill[lab], 1);
    g_list[p] = i;
  }
}

// Positive sampling: one warp per row; g_list unsorted -> full tie-break.
__global__ void k_pos() {
  int w = (blockIdx.x * blockDim.x + threadIdx.x) >> 5;
  int lane = threadIdx.x & 31;
  if (w >= BB) return;
  int i = w;
  int lab = g_lab[i];
  int off = g_off[lab], cnt = g_cnt[lab];
  uint32_t base = (uint32_t)i * (uint32_t)BB;
  uint32_t bestv = 0u; int bestj = 0; int any = 0;
  for (int c = lane; c < cnt; c += 32) {
    int j = g_list[off + c];
    if (j == i) continue;
    uint32_t v = draw_bits(KP.a, KP.b, base + (uint32_t)j) >> 9;
    if (!any || v > bestv || (v == bestv && j < bestj)) { any = 1; bestv = v; bestj = j; }
  }
  for (int o = 16; o; o >>= 1) {
    uint32_t ov = __shfl_down_sync(0xffffffffu, bestv, o);
    int      oj = __shfl_down_sync(0xffffffffu, bestj, o);
    int      oa = __shfl_down_sync(0xffffffffu, any,  o);
    if (oa && (!any || ov > bestv || (ov == bestv && oj < bestj))) {
      any = 1; bestv = ov; bestj = oj;
    }
  }
  if (lane == 0) g_pos[i] = bestj;
}

// Negative sampling (R9): one block per row; 4 independent Threefry chains
// per thread per iteration (ILP), branchless masking. Ascending j per thread
// -> strict > preserves first-occurrence argmax.
__global__ void k_neg() {
  __shared__ unsigned char slab[BB];
  __shared__ uint32_t sv[256];
  __shared__ int sj[256];
  int i = blockIdx.x, t = threadIdx.x;
  {
    const uint32_t* l4 = (const uint32_t*)g_lab8;
    uint32_t* s4 = (uint32_t*)slab;
    for (int j = t; j < BB / 4; j += 256) s4[j] = l4[j];
  }
  __syncthreads();
  unsigned char mylab = slab[i];
  uint32_t base = (uint32_t)i * (uint32_t)BB;
  uint32_t bestv = 0u; int bestj = -1;
#pragma unroll
  for (int s = 0; s < 8; s++) {
    int j0 = t + s * 1024;
    int j1 = j0 + 256, j2 = j0 + 512, j3 = j0 + 768;
    uint32_t d0 = draw_bits(KN.a, KN.b, base + (uint32_t)j0);
    uint32_t d1 = draw_bits(KN.a, KN.b, base + (uint32_t)j1);
    uint32_t d2 = draw_bits(KN.a, KN.b, base + (uint32_t)j2);
    uint32_t d3 = draw_bits(KN.a, KN.b, base + (uint32_t)j3);
    uint32_t v0 = (slab[j0] == mylab) ? 0u : (d0 >> 9);
    uint32_t v1 = (slab[j1] == mylab) ? 0u : (d1 >> 9);
    uint32_t v2 = (slab[j2] == mylab) ? 0u : (d2 >> 9);
    uint32_t v3 = (slab[j3] == mylab) ? 0u : (d3 >> 9);
    if (v0 > bestv) { bestv = v0; bestj = j0; }
    if (v1 > bestv) { bestv = v1; bestj = j1; }
    if (v2 > bestv) { bestv = v2; bestj = j2; }
    if (v3 > bestv) { bestv = v3; bestj = j3; }
  }
  sv[t] = bestv; sj[t] = bestj;
  __syncthreads();
  for (int s = 128; s; s >>= 1) {
    if (t < s) {
      uint32_t ov = sv[t + s]; int oj = sj[t + s];
      if (oj >= 0 && (sj[t] < 0 || ov > sv[t] || (ov == sv[t] && oj < sj[t]))) {
        sv[t] = ov; sj[t] = oj;
      }
    }
    __syncthreads();
  }
  if (t == 0) g_neg[i] = (sj[0] >= 0) ? sj[0] : 0;
}

__global__ void k_mu(const float* __restrict__ F) {
  int c = threadIdx.x;
  int r0 = blockIdx.x * 128;
  float s = 0.f;
  for (int r = 0; r < 128; r++) s += F[(size_t)(r0 + r) * DD + c];
  atomicAdd(&g_musum[c], s);
}

// S = F^T F, upper-triangle 64x64 block tiles (36), split-K (z=8), FFMA2.
__global__ void k_syrk(const float* __restrict__ F) {
  __shared__ float As[16][64];
  __shared__ float Bs[16][64];
  int rem = blockIdx.x, bi = 0;
  while (rem >= 8 - bi) { rem -= 8 - bi; bi++; }
  int bj = bi + rem;
  int i0 = bi * 64, j0 = bj * 64;
  int kb = blockIdx.z * 1024;
  int t = threadIdx.x;
  int tx = t & 15, ty = t >> 4;
  unsigned long long acc2[4][2];
#pragma unroll
  for (int u = 0; u < 4; u++) { acc2[u][0] = 0ull; acc2[u][1] = 0ull; }
  for (int k = kb; k < kb + 1024; k += 16) {
#pragma unroll
    for (int r = 0; r < 4; r++) {
      int e = t + 256 * r, kk = e >> 6, c = e & 63;
      As[kk][c] = F[(size_t)(k + kk) * DD + i0 + c];
      Bs[kk][c] = F[(size_t)(k + kk) * DD + j0 + c];
    }
    __syncthreads();
#pragma unroll
    for (int kk = 0; kk < 16; kk++) {
      unsigned long long aa[4], bb[2];
      const unsigned long long* bp = (const unsigned long long*)&Bs[kk][tx * 4];
      bb[0] = bp[0]; bb[1] = bp[1];
#pragma unroll
      for (int u = 0; u < 4; u++) aa[u] = pack2(As[kk][ty * 4 + u]);
#pragma unroll
      for (int u = 0; u < 4; u++) {
        ffma2(acc2[u][0], aa[u], bb[0]);
        ffma2(acc2[u][1], aa[u], bb[1]);
      }
    }
    __syncthreads();
  }
#pragma unroll
  for (int u = 0; u < 4; u++) {
#pragma unroll
    for (int v2 = 0; v2 < 2; v2++) {
      U64F2 cv; cv.u = acc2[u][v2];
      size_t row = (size_t)(i0 + ty * 4 + u) * DD + j0 + tx * 4 + v2 * 2;
      atomicAdd(&g_S[row],     cv.f.x);
      atomicAdd(&g_S[row + 1], cv.f.y);
    }
  }
}

__global__ void k_makeG() {
  int i = blockIdx.x, j = threadIdx.x;
  const float invB = 1.0f / (float)BB;
  float mui = g_musum[i] * invB;
  float muj = g_musum[j] * invB;
  float s = (i <= j) ? g_S[(size_t)i * DD + j] : g_S[(size_t)j * DD + i];
  float v = s * invB - mui * muj + (i == j ? 1.0f : 0.0f);
  g_G[(size_t)i * DD + j] = v;
}

// H = F * G  (8192x512 @ 512x512), FFMA2 inner loop.
__global__ void k_gemmH(const float* __restrict__ F) {
  __shared__ float As[16][65];
  __shared__ float Bs[16][64];
  int m0 = blockIdx.x * 64, n0 = blockIdx.y * 64;
  int t = threadIdx.x, tx = t & 15, ty = t >> 4;
  unsigned long long acc2[4][2];
#pragma unroll
  for (int u = 0; u < 4; u++) { acc2[u][0] = 0ull; acc2[u][1] = 0ull; }
  for (int k = 0; k < DD; k += 16) {
#pragma unroll
    for (int r = 0; r < 4; r++) {
      int e = t + 256 * r;
      int kk = e & 15, mm = e >> 4;
      As[kk][mm] = F[(size_t)(m0 + mm) * DD + k + kk];
    }
#pragma unroll
    for (int r = 0; r < 4; r++) {
      int e = t + 256 * r, kk = e >> 6, c = e & 63;
      Bs[kk][c] = g_G[(size_t)(k + kk) * DD + n0 + c];
    }
    __syncthreads();
#pragma unroll
    for (int kk = 0; kk < 16; kk++) {
      unsigned long long aa[4], bb[2];
      const unsigned long long* bp = (const unsigned long long*)&Bs[kk][tx * 4];
      bb[0] = bp[0]; bb[1] = bp[1];
#pragma unroll
      for (int u = 0; u < 4; u++) aa[u] = pack2(As[kk][ty * 4 + u]);
#pragma unroll
      for (int u = 0; u < 4; u++) {
        ffma2(acc2[u][0], aa[u], bb[0]);
        ffma2(acc2[u][1], aa[u], bb[1]);
      }
    }
    __syncthreads();
  }
#pragma unroll
  for (int u = 0; u < 4; u++) {
    U64F2 lo, hi; lo.u = acc2[u][0]; hi.u = acc2[u][1];
    float4 o; o.x = lo.f.x; o.y = lo.f.y; o.z = hi.f.x; o.w = hi.f.y;
    *(float4*)&g_H[(size_t)(m0 + ty * 4 + u) * DD + n0 + tx * 4] = o;
  }
}

__global__ void k_q(const float* __restrict__ F) {
  int w = (blockIdx.x * blockDim.x + threadIdx.x) >> 5;
  int lane = threadIdx.x & 31;
  if (w >= BB) return;
  const float* f = F + (size_t)w * DD;
  const float* h = g_H + (size_t)w * DD;
  float s = 0.f;
  for (int c = lane; c < DD; c += 32) s += f[c] * h[c];
  for (int o = 16; o; o >>= 1) s += __shfl_down_sync(0xffffffffu, s, o);
  if (lane == 0) g_q[w] = s;
}

__global__ void k_loss(const float* __restrict__ F) {
  __shared__ float rp[128], rn[128];
  int i = blockIdx.x, t = threadIdx.x;
  int p = g_pos[i], n = g_neg[i];
  float sp = 0.f, sn = 0.f;
  const float* f  = F   + (size_t)i * DD;
  const float* hp = g_H + (size_t)p * DD;
  const float* hn = g_H + (size_t)n * DD;
  for (int c = t; c < DD; c += 128) {
    float fv = f[c];
    sp += fv * hp[c];
    sn += fv * hn[c];
  }
  rp[t] = sp; rn[t] = sn;
  __syncthreads();
  for (int s = 64; s; s >>= 1) {
    if (t < s) { rp[t] += rp[t + s]; rn[t] += rn[t + s]; }
    __syncthreads();
  }
  if (t == 0) {
    int lab = g_lab[i];
    int cnt = g_cnt[lab];
    bool valid = (cnt >= 2) && (cnt < BB);
    if (valid) {
      float dp = sqrtf(g_q[i] + g_q[p] - 2.0f * rp[0] + 1e-8f);
      float dn = sqrtf(g_q[i] + g_q[n] - 2.0f * rn[0] + 1e-8f);
      float per = fmaxf(dp - dn + 1.0f, 0.0f);
      atomicAdd(&g_acc[0], per);
      atomicAdd(&g_acc[1], 1.0f);
    }
  }
}

__global__ void k_final(float* __restrict__ out) {
  out[0] = g_acc[0] / fmaxf(g_acc[1], 1.0f);
}

// ---------------------------------------------------------------------------
extern "C" void kernel_launch(void* const* d_in, const int* in_sizes, int n_in,
                              void* d_out, int out_size) {
  const float* F = (const float*)d_in[0];
  const void*  L = d_in[1];
  float* out = (float*)d_out;

  static cudaStream_t s_samp = nullptr;
  static cudaEvent_t  ev_fork = nullptr, ev_join = nullptr;
  if (s_samp == nullptr) {
    cudaStreamCreateWithFlags(&s_samp, cudaStreamNonBlocking);
    cudaEventCreateWithFlags(&ev_fork, cudaEventDisableTiming);
    cudaEventCreateWithFlags(&ev_join, cudaEventDisableTiming);
  }

  // sampling chain (R9 single-stream layout, faster head)
  cudaEventRecord(ev_fork, 0);
  cudaStreamWaitEvent(s_samp, ev_fork, 0);
  k_zs<<<1, 128, 0, s_samp>>>();
  k_labels<<<8, 1024, 0, s_samp>>>(L);
  k_build<<<1, 1024, 0, s_samp>>>();
  k_pos<<<BB / 8, 256, 0, s_samp>>>();
  k_neg<<<BB, 256, 0, s_samp>>>();
  cudaEventRecord(ev_join, s_samp);

  // metric chain on the main stream
  k_zero<<<256, 256>>>();
  k_mu<<<64, 512>>>(F);
  {
    dim3 g(36, 1, 8);
    k_syrk<<<g, 256>>>(F);
  }
  k_makeG<<<512, 512>>>();
  {
    dim3 g(128, 8);
    k_gemmH<<<g, 256>>>(F);
  }
  k_q<<<BB / 8, 256>>>(F);

  cudaStreamWaitEvent(0, ev_join, 0);
  k_loss<<<BB, 128>>>(F);
  k_final<<<1, 1>>>(out);
}

// round 17
// speedup vs baseline: 1.0993x; 1.0596x over previous
#include <cuda_runtime.h>
#include <stdint.h>
#include <math.h>

// ---------------------------------------------------------------------------
// TripletLossWithCurvature: B=8192, D=512, classes<100
// Bit-exact JAX Threefry-2x32 (partitionable mode).
// R17: GEMMs were smem-port-bound -> 128x128 tiles (256 thr, 8x8/thread),
// LDS.64 row-pair A reads + LDS.128 col-quad B reads (3.4x less smem traffic
// per MAC). SYRK same rework (10 triangle tiles, splitK 8). k_neg outer loop
// unroll 1 (32-draw body was 37KB SASS > 32KB L1.5 I$; 4-draw fits L0).
// ---------------------------------------------------------------------------
#define BB 8192
#define DD 512
#define NCLS 128

__device__ float g_S[DD*DD];
__device__ float g_G[DD*DD];
__device__ float g_H[BB*DD];
__device__ float g_q[BB];
__device__ float g_musum[DD];
__device__ int   g_lab[BB];
__device__ unsigned char g_lab8[BB];
__device__ int   g_cnt[NCLS];
__device__ int   g_off[NCLS];
__device__ int   g_list[BB];
__device__ int   g_pos[BB];
__device__ int   g_neg[BB];
__device__ float g_acc[2];

// ---------------------------------------------------------------------------
// Packed fp32 helpers (exact per-lane IEEE fp32)
// ---------------------------------------------------------------------------
__device__ __forceinline__ void ffma2(unsigned long long &acc,
                                      unsigned long long a2,
                                      unsigned long long b2) {
  asm("fma.rn.f32x2 %0, %1, %2, %0;" : "+l"(acc) : "l"(a2), "l"(b2));
}
__device__ __forceinline__ unsigned long long pack2u(uint32_t x) {
  unsigned long long r;
  asm("mov.b64 %0, {%1, %1};" : "=l"(r) : "r"(x));
  return r;
}
union U64F2 { unsigned long long u; float2 f; };

// ---------------------------------------------------------------------------
// Threefry-2x32, 20 rounds — plain C (forced-pipe variants regressed R8/R12)
// ---------------------------------------------------------------------------
__device__ __forceinline__ void tf_block(uint32_t k0, uint32_t k1,
                                         uint32_t &x0, uint32_t &x1) {
  uint32_t ks2 = k0 ^ k1 ^ 0x1BD11BDAu;
  x0 += k0; x1 += k1;
#define TF_ROT(x,r) (((x) << (r)) | ((x) >> (32 - (r))))
#define TF_RND(r) { x0 += x1; x1 = TF_ROT(x1, r); x1 ^= x0; }
  TF_RND(13) TF_RND(15) TF_RND(26) TF_RND(6)
  x0 += k1;  x1 += ks2 + 1u;
  TF_RND(17) TF_RND(29) TF_RND(16) TF_RND(24)
  x0 += ks2; x1 += k0 + 2u;
  TF_RND(13) TF_RND(15) TF_RND(26) TF_RND(6)
  x0 += k0;  x1 += k1 + 3u;
  TF_RND(17) TF_RND(29) TF_RND(16) TF_RND(24)
  x0 += k1;  x1 += ks2 + 4u;
  TF_RND(13) TF_RND(15) TF_RND(26) TF_RND(6)
  x0 += ks2; x1 += k0 + 5u;
#undef TF_RND
#undef TF_ROT
}
__device__ __forceinline__ uint32_t draw_bits(uint32_t k0, uint32_t k1, uint32_t p) {
  uint32_t x0 = 0u, x1 = p;
  tf_block(k0, k1, x0, x1);
  return x0 ^ x1;
}
struct K2 { uint32_t a, b; };
constexpr uint32_t c_rotl(uint32_t x, int r) { return (x << r) | (x >> (32 - r)); }
constexpr K2 tf_pair(uint32_t k0, uint32_t k1, uint32_t c0, uint32_t c1) {
  uint32_t ks2 = k0 ^ k1 ^ 0x1BD11BDAu;
  uint32_t x0 = c0 + k0, x1 = c1 + k1;
#define CR(r) x0 += x1; x1 = c_rotl(x1, r); x1 ^= x0;
  CR(13) CR(15) CR(26) CR(6)
  x0 += k1;  x1 += ks2 + 1u;
  CR(17) CR(29) CR(16) CR(24)
  x0 += ks2; x1 += k0 + 2u;
  CR(13) CR(15) CR(26) CR(6)
  x0 += k0;  x1 += k1 + 3u;
  CR(17) CR(29) CR(16) CR(24)
  x0 += k1;  x1 += ks2 + 4u;
  CR(13) CR(15) CR(26) CR(6)
  x0 += ks2; x1 += k0 + 5u;
#undef CR
  return K2{x0, x1};
}
constexpr K2 KP = tf_pair(0u, 42u, 0u, 0u);
constexpr K2 KN = tf_pair(0u, 42u, 0u, 1u);

// ---------------------------------------------------------------------------
// Sampling kernels (R16, passing at 400.7us)
// ---------------------------------------------------------------------------
__global__ void k_zero() {
  int idx = blockIdx.x * blockDim.x + threadIdx.x;
  int stride = gridDim.x * blockDim.x;
  for (int i = idx; i < DD*DD; i += stride) g_S[i] = 0.f;
  if (idx < DD) g_musum[idx] = 0.f;
}

__global__ void k_zs() {
  int t = threadIdx.x;
  if (t < NCLS) g_cnt[t] = 0;
  if (t < 2)    g_acc[t] = 0.f;
}

__global__ void k_labels(const void* __restrict__ lraw) {
  __shared__ int s_is64;
  if (threadIdx.x == 0) s_is64 = 1;
  __syncthreads();
  const int* w = (const int*)lraw;
  int b = blockIdx.x;
  if (threadIdx.x < 512) {
    int k = b * 512 + threadIdx.x;
    if (w[2*k + 1] != 0) s_is64 = 0;
  }
  __syncthreads();
  int is64 = s_is64;
  int i = b * 1024 + threadIdx.x;
  int lab = is64 ? (int)(((const long long*)lraw)[i]) : w[i];
  if (lab < 0) lab = 0;
  if (lab >= NCLS) lab = NCLS - 1;
  g_lab[i]  = lab;
  g_lab8[i] = (unsigned char)lab;
  atomicAdd(&g_cnt[lab], 1);
}

__global__ void k_build() {
  __shared__ int s_fill[NCLS];
  int t = threadIdx.x;
  if (t < 32) {
    int c0 = g_cnt[4*t], c1 = g_cnt[4*t+1], c2 = g_cnt[4*t+2], c3 = g_cnt[4*t+3];
    int s = c0 + c1 + c2 + c3;
    int scan = s;
    for (int o = 1; o < 32; o <<= 1) {
      int n = __shfl_up_sync(0xffffffffu, scan, o);
      if (t >= o) scan += n;
    }
    int e = scan - s;
    g_off[4*t]   = e;                s_fill[4*t]   = e;
    g_off[4*t+1] = e + c0;           s_fill[4*t+1] = e + c0;
    g_off[4*t+2] = e + c0 + c1;      s_fill[4*t+2] = e + c0 + c1;
    g_off[4*t+3] = e + c0 + c1 + c2; s_fill[4*t+3] = e + c0 + c1 + c2;
  }
  __syncthreads();
  for (int i = t; i < BB; i += 1024) {
    int lab = g_lab[i];
    int p = atomicAdd(&s_fill[lab], 1);
    g_list[p] = i;
  }
}

__global__ void k_pos() {
  int w = (blockIdx.x * blockDim.x + threadIdx.x) >> 5;
  int lane = threadIdx.x & 31;
  if (w >= BB) return;
  int i = w;
  int lab = g_lab[i];
  int off = g_off[lab], cnt = g_cnt[lab];
  uint32_t base = (uint32_t)i * (uint32_t)BB;
  uint32_t bestv = 0u; int bestj = 0; int any = 0;
  for (int c = lane; c < cnt; c += 32) {
    int j = g_list[off + c];
    if (j == i) continue;
    uint32_t v = draw_bits(KP.a, KP.b, base + (uint32_t)j) >> 9;
    if (!any || v > bestv || (v == bestv && j < bestj)) { any = 1; bestv = v; bestj = j; }
  }
  for (int o = 16; o; o >>= 1) {
    uint32_t ov = __shfl_down_sync(0xffffffffu, bestv, o);
    int      oj = __shfl_down_sync(0xffffffffu, bestj, o);
    int      oa = __shfl_down_sync(0xffffffffu, any,  o);
    if (oa && (!any || ov > bestv || (ov == bestv && oj < bestj))) {
      any = 1; bestv = ov; bestj = oj;
    }
  }
  if (lane == 0) g_pos[i] = bestj;
}

// k_neg: ILP4 body, outer loop NOT unrolled (I-cache: 4-draw body fits L0).
__global__ void k_neg() {
  __shared__ unsigned char slab[BB];
  __shared__ uint32_t sv[256];
  __shared__ int sj[256];
  int i = blockIdx.x, t = threadIdx.x;
  {
    const uint32_t* l4 = (const uint32_t*)g_lab8;
    uint32_t* s4 = (uint32_t*)slab;
    for (int j = t; j < BB / 4; j += 256) s4[j] = l4[j];
  }
  __syncthreads();
  unsigned char mylab = slab[i];
  uint32_t base = (uint32_t)i * (uint32_t)BB;
  uint32_t bestv = 0u; int bestj = -1;
#pragma unroll 1
  for (int s = 0; s < 8; s++) {
    int j0 = t + s * 1024;
    int j1 = j0 + 256, j2 = j0 + 512, j3 = j0 + 768;
    uint32_t d0 = draw_bits(KN.a, KN.b, base + (uint32_t)j0);
    uint32_t d1 = draw_bits(KN.a, KN.b, base + (uint32_t)j1);
    uint32_t d2 = draw_bits(KN.a, KN.b, base + (uint32_t)j2);
    uint32_t d3 = draw_bits(KN.a, KN.b, base + (uint32_t)j3);
    uint32_t v0 = (slab[j0] == mylab) ? 0u : (d0 >> 9);
    uint32_t v1 = (slab[j1] == mylab) ? 0u : (d1 >> 9);
    uint32_t v2 = (slab[j2] == mylab) ? 0u : (d2 >> 9);
    uint32_t v3 = (slab[j3] == mylab) ? 0u : (d3 >> 9);
    if (v0 > bestv) { bestv = v0; bestj = j0; }
    if (v1 > bestv) { bestv = v1; bestj = j1; }
    if (v2 > bestv) { bestv = v2; bestj = j2; }
    if (v3 > bestv) { bestv = v3; bestj = j3; }
  }
  sv[t] = bestv; sj[t] = bestj;
  __syncthreads();
  for (int s = 128; s; s >>= 1) {
    if (t < s) {
      uint32_t ov = sv[t + s]; int oj = sj[t + s];
      if (oj >= 0 && (sj[t] < 0 || ov > sv[t] || (ov == sv[t] && oj < sj[t]))) {
        sv[t] = ov; sj[t] = oj;
      }
    }
    __syncthreads();
  }
  if (t == 0) g_neg[i] = (sj[0] >= 0) ? sj[0] : 0;
}

__global__ void k_mu(const float* __restrict__ F) {
  int c = threadIdx.x;
  int r0 = blockIdx.x * 128;
  float s = 0.f;
  for (int r = 0; r < 128; r++) s += F[(size_t)(r0 + r) * DD + c];
  atomicAdd(&g_musum[c], s);
}

// ---------------------------------------------------------------------------
// Shared 128x128 FFMA2 inner step: thread = 8 rows (ty*8+r) x 8 cols
// (tx*4+{0..3}, 64+tx*4+{0..3}); lanes are col-pairs.
// As/Bs: [kk][dim] with pad 132 (16B-aligned rows).
// ---------------------------------------------------------------------------
#define TP 132

__device__ __forceinline__ void tile_step(const float (*As)[TP],
                                          const float (*Bs)[TP],
                                          int tx, int ty,
                                          unsigned long long acc[8][4]) {
#pragma unroll
  for (int kk = 0; kk < 16; kk++) {
    unsigned long long aa[8];
#pragma unroll
    for (int p = 0; p < 4; p++) {
      unsigned long long a2 = *(const unsigned long long*)&As[kk][ty * 8 + 2 * p];
      aa[2*p]   = pack2u((uint32_t)a2);
      aa[2*p+1] = pack2u((uint32_t)(a2 >> 32));
    }
    ulonglong2 b0 = *(const ulonglong2*)&Bs[kk][tx * 4];
    ulonglong2 b1 = *(const ulonglong2*)&Bs[kk][64 + tx * 4];
#pragma unroll
    for (int r = 0; r < 8; r++) {
      ffma2(acc[r][0], aa[r], b0.x);
      ffma2(acc[r][1], aa[r], b0.y);
      ffma2(acc[r][2], aa[r], b1.x);
      ffma2(acc[r][3], aa[r], b1.y);
    }
  }
}

// S = F^T F, triangle 128x128 tiles (10 of 16), split-K (z=8, 1024 each).
__global__ void __launch_bounds__(256) k_syrk(const float* __restrict__ F) {
  __shared__ __align__(16) float As[16][TP];
  __shared__ __align__(16) float Bs[16][TP];
  int rem = blockIdx.x, bi = 0;
  while (rem >= 4 - bi) { rem -= 4 - bi; bi++; }
  int bj = bi + rem;
  int i0 = bi * 128, j0 = bj * 128;
  int kb = blockIdx.z * 1024;
  int t = threadIdx.x;
  int tx = t & 15, ty = t >> 4;
  unsigned long long acc[8][4];
#pragma unroll
  for (int r = 0; r < 8; r++)
#pragma unroll
    for (int g = 0; g < 4; g++) acc[r][g] = 0ull;

  int c_nn = (t * 4) & 127;        // 0..124 step 4
  int c_kk = t >> 5;               // 0..7
  for (int k = kb; k < kb + 1024; k += 16) {
    // straight copies: As <- F[k..][i0..], Bs <- F[k..][j0..]
    *(float4*)&As[c_kk][c_nn]     = *(const float4*)&F[(size_t)(k + c_kk) * DD + i0 + c_nn];
    *(float4*)&As[c_kk + 8][c_nn] = *(const float4*)&F[(size_t)(k + c_kk + 8) * DD + i0 + c_nn];
    *(float4*)&Bs[c_kk][c_nn]     = *(const float4*)&F[(size_t)(k + c_kk) * DD + j0 + c_nn];
    *(float4*)&Bs[c_kk + 8][c_nn] = *(const float4*)&F[(size_t)(k + c_kk + 8) * DD + j0 + c_nn];
    __syncthreads();
    tile_step(As, Bs, tx, ty, acc);
    __syncthreads();
  }
#pragma unroll
  for (int r = 0; r < 8; r++) {
    size_t row = (size_t)(i0 + ty * 8 + r) * DD;
#pragma unroll
    for (int g = 0; g < 4; g++) {
      U64F2 cv; cv.u = acc[r][g];
      int col = j0 + (g >> 1) * 64 + tx * 4 + (g & 1) * 2;
      atomicAdd(&g_S[row + col],     cv.f.x);
      atomicAdd(&g_S[row + col + 1], cv.f.y);
    }
  }
}

__global__ void k_makeG() {
  int i = blockIdx.x, j = threadIdx.x;
  const float invB = 1.0f / (float)BB;
  float mui = g_musum[i] * invB;
  float muj = g_musum[j] * invB;
  float s = (i <= j) ? g_S[(size_t)i * DD + j] : g_S[(size_t)j * DD + i];
  float v = s * invB - mui * muj + (i == j ? 1.0f : 0.0f);
  g_G[(size_t)i * DD + j] = v;
}

// H = F * G  (8192x512 @ 512x512), 128x128 tiles.
__global__ void __launch_bounds__(256) k_gemmH(const float* __restrict__ F) {
  __shared__ __align__(16) float As[16][TP];   // [kk][mm] (transposed A)
  __shared__ __align__(16) float Bs[16][TP];   // [kk][nn]
  int m0 = blockIdx.x * 128, n0 = blockIdx.y * 128;
  int t = threadIdx.x;
  int tx = t & 15, ty = t >> 4;
  unsigned long long acc[8][4];
#pragma unroll
  for (int r = 0; r < 8; r++)
#pragma unroll
    for (int g = 0; g < 4; g++) acc[r][g] = 0ull;

  int a_mm = t >> 2;               // 0..63 (+64 for second)
  int a_kk = (t & 3) * 4;
  int b_nn = (t * 4) & 127;
  int b_kk = t >> 5;               // 0..7
  for (int k = 0; k < DD; k += 16) {
    float4 av0 = *(const float4*)&F[(size_t)(m0 + a_mm) * DD + k + a_kk];
    float4 av1 = *(const float4*)&F[(size_t)(m0 + a_mm + 64) * DD + k + a_kk];
    As[a_kk+0][a_mm] = av0.x; As[a_kk+1][a_mm] = av0.y;
    As[a_kk+2][a_mm] = av0.z; As[a_kk+3][a_mm] = av0.w;
    As[a_kk+0][a_mm+64] = av1.x; As[a_kk+1][a_mm+64] = av1.y;
    As[a_kk+2][a_mm+64] = av1.z; As[a_kk+3][a_mm+64] = av1.w;
    *(float4*)&Bs[b_kk][b_nn]     = *(const float4*)&g_G[(size_t)(k + b_kk) * DD + n0 + b_nn];
    *(float4*)&Bs[b_kk + 8][b_nn] = *(const float4*)&g_G[(size_t)(k + b_kk + 8) * DD + n0 + b_nn];
    __syncthreads();
    tile_step(As, Bs, tx, ty, acc);
    __syncthreads();
  }
#pragma unroll
  for (int r = 0; r < 8; r++) {
    size_t row = (size_t)(m0 + ty * 8 + r) * DD;
    U64F2 c0, c1, c2, c3;
    c0.u = acc[r][0]; c1.u = acc[r][1]; c2.u = acc[r][2]; c3.u = acc[r][3];
    float4 v0; v0.x = c0.f.x; v0.y = c0.f.y; v0.z = c1.f.x; v0.w = c1.f.y;
    float4 v1; v1.x = c2.f.x; v1.y = c2.f.y; v1.z = c3.f.x; v1.w = c3.f.y;
    *(float4*)&g_H[row + n0 + tx * 4]      = v0;
    *(float4*)&g_H[row + n0 + 64 + tx * 4] = v1;
  }
}

__global__ void k_q(const float* __restrict__ F) {
  int w = (blockIdx.x * blockDim.x + threadIdx.x) >> 5;
  int lane = threadIdx.x & 31;
  if (w >= BB) return;
  const float* f = F + (size_t)w * DD;
  const float* h = g_H + (size_t)w * DD;
  float s = 0.f;
  for (int c = lane; c < DD; c += 32) s += f[c] * h[c];
  for (int o = 16; o; o >>= 1) s += __shfl_down_sync(0xffffffffu, s, o);
  if (lane == 0) g_q[w] = s;
}

__global__ void k_loss(const float* __restrict__ F) {
  __shared__ float rp[128], rn[128];
  int i = blockIdx.x, t = threadIdx.x;
  int p = g_pos[i], n = g_neg[i];
  float sp = 0.f, sn = 0.f;
  const float* f  = F   + (size_t)i * DD;
  const float* hp = g_H + (size_t)p * DD;
  const float* hn = g_H + (size_t)n * DD;
  for (int c = t; c < DD; c += 128) {
    float fv = f[c];
    sp += fv * hp[c];
    sn += fv * hn[c];
  }
  rp[t] = sp; rn[t] = sn;
  __syncthreads();
  for (int s = 64; s; s >>= 1) {
    if (t < s) { rp[t] += rp[t + s]; rn[t] += rn[t + s]; }
    __syncthreads();
  }
  if (t == 0) {
    int lab = g_lab[i];
    int cnt = g_cnt[lab];
    bool valid = (cnt >= 2) && (cnt < BB);
    if (valid) {
      float dp = sqrtf(g_q[i] + g_q[p] - 2.0f * rp[0] + 1e-8f);
      float dn = sqrtf(g_q[i] + g_q[n] - 2.0f * rn[0] + 1e-8f);
      float per = fmaxf(dp - dn + 1.0f, 0.0f);
      atomicAdd(&g_acc[0], per);
      atomicAdd(&g_acc[1], 1.0f);
    }
  }
}

__global__ void k_final(float* __restrict__ out) {
  out[0] = g_acc[0] / fmaxf(g_acc[1], 1.0f);
}

// ---------------------------------------------------------------------------
extern "C" void kernel_launch(void* const* d_in, const int* in_sizes, int n_in,
                              void* d_out, int out_size) {
  const float* F = (const float*)d_in[0];
  const void*  L = d_in[1];
  float* out = (float*)d_out;

  static cudaStream_t s_samp = nullptr;
  static cudaEvent_t  ev_fork = nullptr, ev_join = nullptr;
  if (s_samp == nullptr) {
    cudaStreamCreateWithFlags(&s_samp, cudaStreamNonBlocking);
    cudaEventCreateWithFlags(&ev_fork, cudaEventDisableTiming);
    cudaEventCreateWithFlags(&ev_join, cudaEventDisableTiming);
  }

  // sampling chain
  cudaEventRecord(ev_fork, 0);
  cudaStreamWaitEvent(s_samp, ev_fork, 0);
  k_zs<<<1, 128, 0, s_samp>>>();
  k_labels<<<8, 1024, 0, s_samp>>>(L);
  k_build<<<1, 1024, 0, s_samp>>>();
  k_pos<<<BB / 8, 256, 0, s_samp>>>();
  k_neg<<<BB, 256, 0, s_samp>>>();
  cudaEventRecord(ev_join, s_samp);

  // metric chain
  k_zero<<<256, 256>>>();
  k_mu<<<64, 512>>>(F);
  {
    dim3 g(10, 1, 8);
    k_syrk<<<g, 256>>>(F);
  }
  k_makeG<<<512, 512>>>();
  {
    dim3 g(64, 4);
    k_gemmH<<<g, 256>>>(F);
  }
  k_q<<<BB / 8, 256>>>(F);

  cudaStreamWaitEvent(0, ev_join, 0);
  k_loss<<<BB, 128>>>(F);
  k_final<<<1, 1>>>(out);
}